// round 17
// baseline (speedup 1.0000x reference)
#include <cuda_runtime.h>
#include <cuda_fp16.h>
#include <math.h>
#include <stdint.h>

// Problem constants
#define Bc   4
#define Lc   4096
#define Dc   1024
#define Hc   16
#define Dhc  64
#define Mtot (Bc*Lc)        // 16384 rows
#define NC   64             // scan chunks per sequence
#define CHUNK (Lc/NC)       // 64

// GEMM tiling: 128x128 tile, KT=64 k-chunk (canonical SW128), 2 CTAs/SM
#define MT 128
#define NT 128
#define KT 64               // k per stage (128 bytes/row = SW128 atom)
#define NKC (Dc/KT)         // 16 k-chunks
#define TILE_B (MT*KT*2)            // 16384 bytes per operand tile
#define OFF_AH 0
#define OFF_WH (TILE_B)
#define STAGE_BYTES (2*TILE_B)      // 32768
#define NSTAGE 3
#define GEMM_SMEM (NSTAGE*STAGE_BYTES)     // 98304 -> 2 CTAs/SM

// Canonical SW128 swizzle for 128-byte rows (verified pattern)
#define SWZ128(off) ((uint32_t)(off) ^ (((uint32_t)(off) >> 3) & 0x70u))

// ---------------------------------------------------------------------------
// Scratch (__device__ globals per allocation-free rule)
// ---------------------------------------------------------------------------
__device__ __half g_qh[Mtot*Dc];               // q (fp16)
__device__ __half g_vh[Mtot*Dc];               // v (fp16)
__device__ __half g_gh[Mtot*Dc];               // gate pre-activation (fp16)
__device__ __half g_ret[Mtot*Dc];              // ret = q*s (fp16)
__device__ float g_chunkS[Bc*Hc*NC*Dhc];
__device__ float g_carry [Bc*Hc*NC*Dhc];
__device__ __half g_xh[Mtot*Dc];               // x in fp16
__device__ __half g_zh[Mtot*Dc];               // z in fp16
__device__ __half g_wh[4*Dc*Dc];               // Wq,Wv,Wg,Wo in fp16

// ---------------------------------------------------------------------------
// PTX helpers
// ---------------------------------------------------------------------------
__device__ __forceinline__ uint32_t smem_to_u32(const void* p) {
    uint32_t a;
    asm("{ .reg .u64 t; cvta.to.shared.u64 t, %1; cvt.u32.u64 %0, t; }" : "=r"(a) : "l"(p));
    return a;
}

#define CP16(dst, src) \
    asm volatile("cp.async.cg.shared.global [%0], [%1], 16;" :: "r"(dst), "l"(src) : "memory")

__device__ __forceinline__ void ldsm_x4(uint32_t (&r)[4], uint32_t addr) {
    asm volatile("ldmatrix.sync.aligned.m8n8.x4.shared.b16 {%0,%1,%2,%3}, [%4];"
        : "=r"(r[0]), "=r"(r[1]), "=r"(r[2]), "=r"(r[3]) : "r"(addr));
}

__device__ __forceinline__ void mma16816(float (&c)[4], const uint32_t (&a)[4],
                                         uint32_t b0, uint32_t b1) {
    asm volatile("mma.sync.aligned.m16n8k16.row.col.f32.f16.f16.f32 "
        "{%0,%1,%2,%3}, {%4,%5,%6,%7}, {%8,%9}, {%0,%1,%2,%3};"
        : "+f"(c[0]), "+f"(c[1]), "+f"(c[2]), "+f"(c[3])
        : "r"(a[0]), "r"(a[1]), "r"(a[2]), "r"(a[3]), "r"(b0), "r"(b1));
}

// ---------------------------------------------------------------------------
// Single fused fp32 -> fp16 convert: x followed by 4 weights, flat 1D grid,
// zero empty blocks (exact element count).
// ---------------------------------------------------------------------------
#define XQUADS (Mtot*Dc/4)          // 4,194,304
#define WQUADS (Dc*Dc/4)            // 262,144
#define TOTQUADS (XQUADS + 4*WQUADS)

struct Cvt1Args {
    const float* x;
    const float* w[4];
    __half* xh;
    __half* wh;     // 4 weights contiguous
};

__global__ __launch_bounds__(256)
void cvt_all_kernel(const Cvt1Args args)
{
    int i = blockIdx.x * 256 + threadIdx.x;
    if (i >= TOTQUADS) return;

    const float* s;
    __half* d;
    if (i < XQUADS) {
        s = args.x + (size_t)i * 4;
        d = args.xh + (size_t)i * 4;
    } else {
        int j = i - XQUADS;
        int z = j / WQUADS;
        int w = j - z * WQUADS;
        s = args.w[z] + (size_t)w * 4;
        d = args.wh + (size_t)z * Dc * Dc + (size_t)w * 4;
    }
    float4 f = *(const float4*)s;
    __half2 hp0 = __floats2half2_rn(f.x, f.y);
    __half2 hp1 = __floats2half2_rn(f.z, f.w);
    uint2 hv;
    hv.x = *(uint32_t*)&hp0; hv.y = *(uint32_t*)&hp1;
    *(uint2*)d = hv;
}

// ---------------------------------------------------------------------------
// mma.sync GEMM (UNCHANGED from verified 436.9us config)
// ---------------------------------------------------------------------------
template <typename OutT>
struct GemmArgs {
    const __half* Ah;
    const __half* Wh[3];
    OutT* C[3];
};

template <typename OutT>
__global__ __launch_bounds__(256, 2)
void gemm_mma(const GemmArgs<OutT> args)
{
    extern __shared__ char smem[];
    const uint32_t sbase = smem_to_u32(smem);
    const int tid  = threadIdx.x;
    const int lane = tid & 31;
    const int wid  = tid >> 5;
    const int wm   = wid & 3;
    const int wn   = wid >> 2;
    const int bn   = blockIdx.x * NT;
    const int bm   = blockIdx.y * MT;
    const int z    = blockIdx.z;

    const __half* __restrict__ Ah = args.Ah;
    const __half* __restrict__ Wh = args.Wh[z];
    OutT* __restrict__ C = args.C[z];

    auto load_stage = [&](int st, int kc) {
        const uint32_t sb = sbase + (uint32_t)st * STAGE_BYTES;
        const int k0 = kc * KT;
        #pragma unroll
        for (int it = 0; it < 4; it++) {
            int idx = tid + it * 256;
            int row = idx >> 3;
            int ch  = idx & 7;
            uint32_t sw = SWZ128((uint32_t)row * 128 + (uint32_t)ch * 16);
            const __half* pa = Ah + (size_t)(bm + row) * Dc + k0 + ch * 8;
            const __half* pw = Wh + (size_t)(bn + row) * Dc + k0 + ch * 8;
            CP16(sb + OFF_AH + sw, pa);
            CP16(sb + OFF_WH + sw, pw);
        }
        asm volatile("cp.async.commit_group;" ::: "memory");
    };

    float c[2][8][4];
    #pragma unroll
    for (int i = 0; i < 2; i++)
        #pragma unroll
        for (int j = 0; j < 8; j++)
            #pragma unroll
            for (int k = 0; k < 4; k++) c[i][j][k] = 0.0f;

    load_stage(0, 0);
    load_stage(1, 1);

    const int a_r  = lane & 15;
    const int a_kc = lane >> 4;
    const int b_r  = ((lane >> 4) << 3) + (lane & 7);
    const int b_kc = (lane >> 3) & 1;

    for (int kc = 0; kc < NKC; kc++) {
        const int st = kc % NSTAGE;
        asm volatile("cp.async.wait_group 1;" ::: "memory");
        __syncthreads();

        if (kc + 2 < NKC) load_stage((kc + 2) % NSTAGE, kc + 2);
        else asm volatile("cp.async.commit_group;" ::: "memory");

        const uint32_t sb = sbase + (uint32_t)st * STAGE_BYTES;

        #pragma unroll
        for (int ks = 0; ks < 4; ks++) {
            uint32_t ah[2][4];
            #pragma unroll
            for (int mi = 0; mi < 2; mi++) {
                int row = wm * 32 + mi * 16 + a_r;
                uint32_t off = (uint32_t)row * 128 + (uint32_t)(ks * 2 + a_kc) * 16;
                ldsm_x4(ah[mi], sb + OFF_AH + SWZ128(off));
            }
            #pragma unroll
            for (int half = 0; half < 2; half++) {
                uint32_t bh[2][4];
                #pragma unroll
                for (int p = 0; p < 2; p++) {
                    int pr  = half * 2 + p;
                    int row = wn * 64 + pr * 16 + b_r;
                    uint32_t off = (uint32_t)row * 128 + (uint32_t)(ks * 2 + b_kc) * 16;
                    ldsm_x4(bh[p], sb + OFF_WH + SWZ128(off));
                }
                #pragma unroll
                for (int mi = 0; mi < 2; mi++)
                    #pragma unroll
                    for (int p = 0; p < 2; p++) {
                        int ni = (half * 2 + p) * 2;
                        mma16816(c[mi][ni+0], ah[mi], bh[p][0], bh[p][1]);
                        mma16816(c[mi][ni+1], ah[mi], bh[p][2], bh[p][3]);
                    }
            }
        }
    }

    const int er = lane >> 2;
    const int ec = (lane & 3) * 2;
    #pragma unroll
    for (int mi = 0; mi < 2; mi++) {
        #pragma unroll
        for (int ni = 0; ni < 8; ni++) {
            size_t r0g = (size_t)(bm + wm * 32 + mi * 16 + er);
            size_t cg  = (size_t)(bn + wn * 64 + ni * 8 + ec);
            if constexpr (sizeof(OutT) == 4) {
                float2* p0 = (float2*)((float*)C + r0g * Dc + cg);
                float2* p1 = (float2*)((float*)C + (r0g + 8) * Dc + cg);
                *p0 = make_float2(c[mi][ni][0], c[mi][ni][1]);
                *p1 = make_float2(c[mi][ni][2], c[mi][ni][3]);
            } else {
                __half2 h0 = __floats2half2_rn(c[mi][ni][0], c[mi][ni][1]);
                __half2 h1 = __floats2half2_rn(c[mi][ni][2], c[mi][ni][3]);
                *(__half2*)((__half*)C + r0g * Dc + cg)       = h0;
                *(__half2*)((__half*)C + (r0g + 8) * Dc + cg) = h1;
            }
        }
    }
}

// ---------------------------------------------------------------------------
// Retention scan (half2 lanes, NC=64)
// ---------------------------------------------------------------------------
__device__ __forceinline__ float lam_of(const float* beta, int h)
{
    float lam = 1.0f - exp2f(-beta[h]);
    lam = fmaxf(lam, 1.17549435e-38f);
    lam = fminf(lam, 1.0f);
    return lam;
}

__global__ __launch_bounds__(128)
void scan_pass1(const __half2* __restrict__ v2, const float* __restrict__ beta)
{
    int task = blockIdx.x * 4 + (threadIdx.x >> 5);
    int lane = threadIdx.x & 31;
    int cc  = task % NC;
    int bh  = task / NC;
    int h   = bh % Hc;
    int b   = bh / Hc;

    float lam = lam_of(beta, h);
    size_t off = (((size_t)(b*Lc + cc*CHUNK)) * Dc + h*Dhc) / 2 + lane;

    float s0 = 0.0f, s1 = 0.0f;
    #pragma unroll
    for (int t0 = 0; t0 < CHUNK; t0 += 16) {
        __half2 vals[16];
        #pragma unroll
        for (int j = 0; j < 16; j++)
            vals[j] = v2[off + (size_t)j * (Dc/2)];
        #pragma unroll
        for (int j = 0; j < 16; j++) {
            float2 f = __half22float2(vals[j]);
            s0 = fmaf(lam, s0, f.x);
            s1 = fmaf(lam, s1, f.y);
        }
        off += (size_t)16 * (Dc/2);
    }
    size_t pos = (size_t)(bh*NC + cc)*Dhc + 2*lane;
    g_chunkS[pos]   = s0;
    g_chunkS[pos+1] = s1;
}

__global__ __launch_bounds__(256)
void scan_pass2(const float* __restrict__ beta)
{
    int idx = blockIdx.x * blockDim.x + threadIdx.x;
    int dh  = idx & 63;
    int bh  = idx >> 6;
    int h   = bh & (Hc - 1);

    float lam = lam_of(beta, h);
    float lamP = lam;
    #pragma unroll
    for (int i = 0; i < 6; i++) lamP = lamP * lamP;   // lam^64

    float cs[NC];
    #pragma unroll
    for (int cc = 0; cc < NC; cc++)
        cs[cc] = g_chunkS[(size_t)(bh*NC + cc)*Dhc + dh];

    float carry = 0.0f;
    #pragma unroll
    for (int cc = 0; cc < NC; cc++) {
        g_carry[(size_t)(bh*NC + cc)*Dhc + dh] = carry;
        carry = fmaf(lamP, carry, cs[cc]);
    }
}

// Pass 3: 256-thread blocks, 8 warp-tasks per CTA.
__global__ __launch_bounds__(256)
void scan_pass3(const __half2* __restrict__ v2, const __half2* __restrict__ q2,
                __half2* __restrict__ ret2, const float* __restrict__ beta)
{
    int task = blockIdx.x * 8 + (threadIdx.x >> 5);
    int lane = threadIdx.x & 31;
    int cc  = task % NC;
    int bh  = task / NC;
    int h   = bh % Hc;
    int b   = bh / Hc;

    float lam = lam_of(beta, h);
    size_t off = (((size_t)(b*Lc + cc*CHUNK)) * Dc + h*Dhc) / 2 + lane;

    size_t cpos = (size_t)(bh*NC + cc)*Dhc + 2*lane;
    float s0 = g_carry[cpos];
    float s1 = g_carry[cpos+1];

    #pragma unroll
    for (int t0 = 0; t0 < CHUNK; t0 += 16) {
        __half2 vv[16], qq[16];
        #pragma unroll
        for (int j = 0; j < 16; j++) {
            vv[j] = v2[off + (size_t)j * (Dc/2)];
            qq[j] = q2[off + (size_t)j * (Dc/2)];
        }
        #pragma unroll
        for (int j = 0; j < 16; j++) {
            float2 fv = __half22float2(vv[j]);
            float2 fq = __half22float2(qq[j]);
            s0 = fmaf(lam, s0, fv.x);
            s1 = fmaf(lam, s1, fv.y);
            ret2[off + (size_t)j * (Dc/2)] = __floats2half2_rn(fq.x * s0, fq.y * s1);
        }
        off += (size_t)16 * (Dc/2);
    }
}

// ---------------------------------------------------------------------------
// Fused LayerNorm(ret) * SiLU(gate) -> z fp16.
// 128 threads x uint4 (8 halves/thread), fp32 reduce.
// ---------------------------------------------------------------------------
__global__ __launch_bounds__(128)
void ln_gate_kernel(const __half* __restrict__ ret, const __half* __restrict__ gate,
                    const float* __restrict__ gamma, const float* __restrict__ lbeta,
                    __half* __restrict__ zh)
{
    const size_t row = blockIdx.x;
    const int tid = threadIdx.x;

    uint4 rv = ((const uint4*)(ret  + row*Dc))[tid];
    uint4 gv = ((const uint4*)(gate + row*Dc))[tid];
    float r[8], g[8];
    {
        __half2 h0 = *(__half2*)&rv.x, h1 = *(__half2*)&rv.y;
        __half2 h2 = *(__half2*)&rv.z, h3 = *(__half2*)&rv.w;
        float2 f0 = __half22float2(h0), f1 = __half22float2(h1);
        float2 f2 = __half22float2(h2), f3 = __half22float2(h3);
        r[0]=f0.x; r[1]=f0.y; r[2]=f1.x; r[3]=f1.y;
        r[4]=f2.x; r[5]=f2.y; r[6]=f3.x; r[7]=f3.y;
        __half2 k0 = *(__half2*)&gv.x, k1 = *(__half2*)&gv.y;
        __half2 k2 = *(__half2*)&gv.z, k3 = *(__half2*)&gv.w;
        float2 e0 = __half22float2(k0), e1 = __half22float2(k1);
        float2 e2 = __half22float2(k2), e3 = __half22float2(k3);
        g[0]=e0.x; g[1]=e0.y; g[2]=e1.x; g[3]=e1.y;
        g[4]=e2.x; g[5]=e2.y; g[6]=e3.x; g[7]=e3.y;
    }

    float s = 0.0f, ss = 0.0f;
    #pragma unroll
    for (int j = 0; j < 8; j++) { s += r[j]; ss += r[j]*r[j]; }

    #pragma unroll
    for (int o = 16; o > 0; o >>= 1) {
        s  += __shfl_xor_sync(0xffffffffu, s,  o);
        ss += __shfl_xor_sync(0xffffffffu, ss, o);
    }
    __shared__ float shs[4], shq[4];
    if ((tid & 31) == 0) { shs[tid>>5] = s; shq[tid>>5] = ss; }
    __syncthreads();

    float tot = shs[0] + shs[1] + shs[2] + shs[3];
    float totq = shq[0] + shq[1] + shq[2] + shq[3];

    const float inv = 1.0f / (float)Dc;
    float mu   = tot * inv;
    float var  = totq * inv - mu * mu;
    float rstd = rsqrtf(var + 1e-5f);

    const float4 gm0 = ((const float4*)gamma)[tid*2];
    const float4 gm1 = ((const float4*)gamma)[tid*2+1];
    const float4 bt0 = ((const float4*)lbeta)[tid*2];
    const float4 bt1 = ((const float4*)lbeta)[tid*2+1];
    float gmv[8] = {gm0.x, gm0.y, gm0.z, gm0.w, gm1.x, gm1.y, gm1.z, gm1.w};
    float btv[8] = {bt0.x, bt0.y, bt0.z, bt0.w, bt1.x, bt1.y, bt1.z, bt1.w};

    float o[8];
    #pragma unroll
    for (int j = 0; j < 8; j++) {
        float y = (r[j] - mu) * rstd * gmv[j] + btv[j];
        o[j] = y * (g[j] / (1.0f + expf(-g[j])));
    }

    uint4 hv;
    __half2 p0 = __floats2half2_rn(o[0], o[1]);
    __half2 p1 = __floats2half2_rn(o[2], o[3]);
    __half2 p2 = __floats2half2_rn(o[4], o[5]);
    __half2 p3 = __floats2half2_rn(o[6], o[7]);
    hv.x = *(uint32_t*)&p0; hv.y = *(uint32_t*)&p1;
    hv.z = *(uint32_t*)&p2; hv.w = *(uint32_t*)&p3;
    ((uint4*)(zh + row*Dc))[tid] = hv;
}

// ---------------------------------------------------------------------------
// Launch
// ---------------------------------------------------------------------------
extern "C" void kernel_launch(void* const* d_in, const int* in_sizes, int n_in,
                              void* d_out, int out_size)
{
    const float* x      = (const float*)d_in[0];
    const float* Wq     = (const float*)d_in[1];
    const float* Wv     = (const float*)d_in[2];
    const float* Wo     = (const float*)d_in[3];
    const float* Wg     = (const float*)d_in[4];
    const float* beta   = (const float*)d_in[5];
    const float* gamma  = (const float*)d_in[6];
    const float* lbeta  = (const float*)d_in[7];
    float* out          = (float*)d_out;

    __half *qh, *vh, *gh, *ret, *xh, *zh, *wh;
    cudaGetSymbolAddress((void**)&qh, g_qh);
    cudaGetSymbolAddress((void**)&vh, g_vh);
    cudaGetSymbolAddress((void**)&gh, g_gh);
    cudaGetSymbolAddress((void**)&ret, g_ret);
    cudaGetSymbolAddress((void**)&xh, g_xh);
    cudaGetSymbolAddress((void**)&zh, g_zh);
    cudaGetSymbolAddress((void**)&wh, g_wh);

    cudaFuncSetAttribute((const void*)gemm_mma<__half>, cudaFuncAttributeMaxDynamicSharedMemorySize, GEMM_SMEM);
    cudaFuncSetAttribute((const void*)gemm_mma<float>,  cudaFuncAttributeMaxDynamicSharedMemorySize, GEMM_SMEM);

    // Single fused convert: x + 4 weights, exact flat grid
    Cvt1Args ca;
    ca.x = x; ca.xh = xh; ca.wh = wh;
    ca.w[0] = Wq; ca.w[1] = Wv; ca.w[2] = Wg; ca.w[3] = Wo;
    cvt_all_kernel<<<(TOTQUADS + 255)/256, 256>>>(ca);

    // Fused q/v/g projection GEMMs (fp16 outputs)
    GemmArgs<__half> a1;
    a1.Ah = xh;
    a1.Wh[0] = wh + 0*(size_t)Dc*Dc; a1.C[0] = qh;
    a1.Wh[1] = wh + 1*(size_t)Dc*Dc; a1.C[1] = vh;
    a1.Wh[2] = wh + 2*(size_t)Dc*Dc; a1.C[2] = gh;
    dim3 grid_qvg(Dc/NT, Mtot/MT, 3);   // (8, 128, 3)
    gemm_mma<__half><<<grid_qvg, 256, GEMM_SMEM>>>(a1);

    // Scan
    scan_pass1<<<(Bc*Hc*NC)/4, 128>>>((const __half2*)vh, beta);
    scan_pass2<<<(Bc*Hc*Dhc)/256, 256>>>(beta);
    scan_pass3<<<(Bc*Hc*NC)/8, 256>>>((const __half2*)vh, (const __half2*)qh,
                                      (__half2*)ret, beta);

    ln_gate_kernel<<<Mtot, 128>>>(ret, gh, gamma, lbeta, zh);

    // Output GEMM (fp32 output)
    GemmArgs<float> a2;
    a2.Ah = zh;
    a2.Wh[0] = wh + 3*(size_t)Dc*Dc; a2.C[0] = out;
    a2.Wh[1] = a2.Wh[0]; a2.C[1] = out;
    a2.Wh[2] = a2.Wh[0]; a2.C[2] = out;
    dim3 grid_o(Dc/NT, Mtot/MT, 1);     // (8, 128, 1)
    gemm_mma<float><<<grid_o, 256, GEMM_SMEM>>>(a2);
}